// round 11
// baseline (speedup 1.0000x reference)
#include <cuda_runtime.h>
#include <cuda_fp16.h>
#include <cstdint>

// Problem constants
#define BQ    2
#define NPT   65536
#define KN    16
#define CIN   64
#define CADD  3
#define CTOT  67
#define CPAD  68
#define CMID  16
#define INF   1072        // CTOT * CMID
#define KPAD  1088        // padded to 17*64
#define COUT  128
#define NPTS  (BQ * NPT)  // 131072

// fp16 scratch: pconv output [M][KPAD] (285 MB) + converted weights
__device__ __half g_a16[(size_t)NPTS * KPAD];
__device__ __half g_w16[(size_t)COUT * KPAD];
__device__ int g_idx_is64;

// ---------------------------------------------------------------------------
// Helpers
// ---------------------------------------------------------------------------
__device__ __forceinline__ uint32_t smem_u32(const void* p) {
    uint32_t a;
    asm("{ .reg .u64 t; cvta.to.shared.u64 t, %1; cvt.u32.u64 %0, t; }"
        : "=r"(a) : "l"(p));
    return a;
}
__device__ __forceinline__ uint32_t lds32(uint32_t a) {
    uint32_t v;
    asm volatile("ld.shared.b32 %0, [%1];" : "=r"(v) : "r"(a));
    return v;
}
__device__ __forceinline__ void cp16(uint32_t sa, const void* g) {
    asm volatile("cp.async.cg.shared.global [%0], [%1], 16;" :: "r"(sa), "l"(g));
}
#define CP_COMMIT() asm volatile("cp.async.commit_group;" ::: "memory")
#define CP_WAIT1()  asm volatile("cp.async.wait_group 1;" ::: "memory")

__device__ __forceinline__ void mma16816(float* c, uint32_t a0, uint32_t a1,
                                         uint32_t a2, uint32_t a3,
                                         uint32_t b0, uint32_t b1) {
    asm volatile(
        "mma.sync.aligned.m16n8k16.row.col.f32.f16.f16.f32 "
        "{%0,%1,%2,%3}, {%4,%5,%6,%7}, {%8,%9}, {%0,%1,%2,%3};"
        : "+f"(c[0]), "+f"(c[1]), "+f"(c[2]), "+f"(c[3])
        : "r"(a0), "r"(a1), "r"(a2), "r"(a3), "r"(b0), "r"(b1));
}

// Packed f32x2 (sm_100+)
__device__ __forceinline__ unsigned long long pack2(float lo, float hi) {
    unsigned long long r;
    asm("mov.b64 %0, {%1, %2};" : "=l"(r) : "f"(lo), "f"(hi));
    return r;
}
__device__ __forceinline__ void unpack2(unsigned long long v, float& lo, float& hi) {
    asm("mov.b64 {%0, %1}, %2;" : "=f"(lo), "=f"(hi) : "l"(v));
}
__device__ __forceinline__ void ffma2(unsigned long long& d,
                                      unsigned long long a,
                                      unsigned long long b) {
    asm("fma.rn.f32x2 %0, %1, %2, %0;" : "+l"(d) : "l"(a), "l"(b));
}

// ---------------------------------------------------------------------------
// Kernel 0: detect index dtype (int64 vs int32 layout). Values < 65536, so an
// int64 buffer has all-zero odd 32-bit words. Reads 128B, in-bounds either way.
// ---------------------------------------------------------------------------
__global__ void detect_idx_kernel(const int* __restrict__ idx_raw)
{
    if (threadIdx.x == 0 && blockIdx.x == 0) {
        int nz = 0;
#pragma unroll
        for (int i = 1; i < 32; i += 2) nz |= idx_raw[i];
        g_idx_is64 = (nz == 0) ? 1 : 0;
    }
}

// ---------------------------------------------------------------------------
// Kernel W: convert linear_weight to fp16, zero-padded to KPAD
// ---------------------------------------------------------------------------
__global__ void wconv_kernel(const float* __restrict__ W)
{
    int idx = blockIdx.x * 256 + threadIdx.x;
    if (idx >= COUT * KPAD) return;
    int row = idx / KPAD, col = idx % KPAD;
    float x = (col < INF) ? W[row * INF + col] : 0.f;
    g_w16[idx] = __float2half_rn(x);
}

// ---------------------------------------------------------------------------
// fp16 store of a 16-float pair-block held as 8 packed f32x2
// ---------------------------------------------------------------------------
__device__ __forceinline__ void store_half16p(__half* dst,
                                              const unsigned long long* a)
{
    uint32_t h[8];
#pragma unroll
    for (int q = 0; q < 8; ++q) {
        float lo, hi;
        unpack2(a[q], lo, hi);
        __half2 v = __float22half2_rn(make_float2(lo, hi));
        h[q] = *(uint32_t*)&v;
    }
    ((uint4*)dst)[0] = make_uint4(h[0], h[1], h[2], h[3]);
    ((uint4*)dst)[1] = make_uint4(h[4], h[5], h[6], h[7]);
}

// ---------------------------------------------------------------------------
// Kernel 1: gather + weighted neighbor reduction -> fp16 rows [KPAD]
// One warp per point; 4 points per 128-thread block.
// Inner product done with packed fma.rn.f32x2 (j-pairs), halving FMA issue.
// ---------------------------------------------------------------------------
__global__ void __launch_bounds__(128, 5)
pconv_kernel(const float* __restrict__ input_feat,
             const int* __restrict__ nbr_raw,
             const float* __restrict__ wnet,
             const float* __restrict__ addf)
{
    const int warp = threadIdx.x >> 5;
    const int lane = threadIdx.x & 31;
    const int p = blockIdx.x * 4 + warp;
    const int b = p >> 16;

    __shared__ __align__(16) float fs[4][KN][CPAD];
    __shared__ __align__(16) float ws[4][KN][CMID];

    const float* featbase = input_feat + (size_t)b * NPT * CIN;
    const float* wp = wnet + (size_t)p * KN * CMID;
    const float* ap = addf + (size_t)p * KN * CADD;

    {
        const float4* w4 = (const float4*)wp;
        float4* s4 = (float4*)(&ws[warp][0][0]);
        s4[lane]      = w4[lane];
        s4[lane + 32] = w4[lane + 32];
    }

    const int stride = g_idx_is64 ? 2 : 1;
    const int* inds = nbr_raw + (size_t)p * KN * stride;
    int myidx = 0;
    if (lane < KN) {
        myidx = inds[lane * stride];
        myidx = min(max(myidx, 0), NPT - 1);
    }

#pragma unroll 4
    for (int k = 0; k < KN; ++k) {
        int r = __shfl_sync(0xffffffffu, myidx, k);
        const float* src = featbase + (size_t)r * CIN;
        fs[warp][k][lane]      = src[lane];
        fs[warp][k][lane + 32] = src[lane + 32];
    }
    if (lane < KN) {
        fs[warp][lane][64] = ap[lane * 3 + 0];
        fs[warp][lane][65] = ap[lane * 3 + 1];
        fs[warp][lane][66] = ap[lane * 3 + 2];
    }
    __syncwarp();

    // Packed accumulators: 8 j-pairs per owned c (c = lane, lane+32, lane+64)
    unsigned long long acc0[8], acc1[8], acc2[8];
#pragma unroll
    for (int q = 0; q < 8; ++q) { acc0[q] = 0ull; acc1[q] = 0ull; acc2[q] = 0ull; }

    const bool has_c2 = (lane < 3);
#pragma unroll
    for (int k = 0; k < KN; ++k) {
        // weightnet row k as 8 packed pairs (LDS.64, 8B-aligned)
        unsigned long long wk2[8];
        const unsigned long long* wrow =
            (const unsigned long long*)(&ws[warp][k][0]);
#pragma unroll
        for (int q = 0; q < 8; ++q) wk2[q] = wrow[q];

        const float f0 = fs[warp][k][lane];
        const float f1 = fs[warp][k][lane + 32];
        const float f2 = has_c2 ? fs[warp][k][lane + 64] : 0.f;
        const unsigned long long d0 = pack2(f0, f0);
        const unsigned long long d1 = pack2(f1, f1);
        const unsigned long long d2 = pack2(f2, f2);
#pragma unroll
        for (int q = 0; q < 8; ++q) {
            ffma2(acc0[q], d0, wk2[q]);
            ffma2(acc1[q], d1, wk2[q]);
            ffma2(acc2[q], d2, wk2[q]);
        }
    }

    __half* orow = g_a16 + (size_t)p * KPAD;
    store_half16p(orow + (size_t)lane * CMID,        acc0);
    store_half16p(orow + (size_t)(lane + 32) * CMID, acc1);
    if (has_c2)
        store_half16p(orow + (size_t)(lane + 64) * CMID, acc2);
    if (lane == 3) {   // zero pad cols 1072..1087
        uint4 z = make_uint4(0, 0, 0, 0);
        ((uint4*)(orow + INF))[0] = z;
        ((uint4*)(orow + INF))[1] = z;
    }
}

// ---------------------------------------------------------------------------
// Kernel 2: fp16 mma.sync GEMM   out[M,128] = A[M,KPAD] @ W[128,KPAD]^T + bias
// CTA 128x128, 8 warps (2x4), warp tile 64x32 = 4x4 m16n8k16 frags, fp32 acc.
// K staged 64-wide, 3-stage cp.async pipeline (wait_group 1): each copy hides
// under two stages of MMA compute. SMEM pitch 144B (bank-conflict-free).
// ---------------------------------------------------------------------------
#define KSTG   64
#define PITCH  144                    // bytes per smem row (72 halves)
#define TILEB  (128 * PITCH)          // 18432 B per matrix per stage
#define STAGEB (2 * TILEB)            // A + W per stage
#define NPIPE  3
#define OFF_BIAS (NPIPE * STAGEB)
#define SMEM_BYTES (NPIPE * STAGEB + 512)   // 111104
#define NSTG   (KPAD / KSTG)          // 17

__global__ void __launch_bounds__(256, 2)
gemm_mma_kernel(const float* __restrict__ bias, float* __restrict__ out)
{
    extern __shared__ char smem[];
    const uint32_t sb = smem_u32(smem);
    const int t = threadIdx.x;
    const int wid = t >> 5, lane = t & 31;
    const int wm = wid >> 2, wn = wid & 3;          // warp grid 2(M) x 4(N)
    const int g = lane >> 2, tg = lane & 3;         // mma lane decomposition
    const int m0 = blockIdx.x * 128;

    if (t < COUT) ((float*)(smem + OFF_BIAS))[t] = bias[t];

    const int lrow = t >> 1;                        // 0..127
    const int lc8a = (t & 1) * 4;                   // base c8 (0 or 4)

    auto issue_stage = [&](int s) {
        const int buf = s % NPIPE;
        const int k0 = s * KSTG;
#pragma unroll
        for (int i = 0; i < 4; ++i) {
            const int c8 = lc8a + i;                // 8 halves each
            const uint32_t so = lrow * PITCH + c8 * 16;
            cp16(sb + buf * STAGEB + so,
                 g_a16 + (size_t)(m0 + lrow) * KPAD + k0 + c8 * 8);
            cp16(sb + buf * STAGEB + TILEB + so,
                 g_w16 + (size_t)lrow * KPAD + k0 + c8 * 8);
        }
        CP_COMMIT();
    };

    float acc[4][4][4];
#pragma unroll
    for (int mi = 0; mi < 4; ++mi)
#pragma unroll
        for (int ni = 0; ni < 4; ++ni)
#pragma unroll
            for (int q = 0; q < 4; ++q) acc[mi][ni][q] = 0.f;

    issue_stage(0);
    issue_stage(1);

    for (int s = 0; s < NSTG; ++s) {
        CP_WAIT1();          // stage s's copy complete (s+1 may be in flight)
        __syncthreads();     // all warps past compute of s-1; buffer reuse safe
        if (s + 2 < NSTG) issue_stage(s + 2);

        const int buf = s % NPIPE;
        const uint32_t aB = sb + buf * STAGEB + (wm * 64 + g) * PITCH + tg * 4;
        const uint32_t bB = sb + buf * STAGEB + TILEB + (wn * 32 + g) * PITCH + tg * 4;
#pragma unroll
        for (int kk = 0; kk < 4; ++kk) {            // 4 k16-steps per stage
            const uint32_t ka = aB + kk * 32;       // 16 halves = 32 B
            const uint32_t kb = bB + kk * 32;
            uint32_t a[4][4], bfr[4][2];
#pragma unroll
            for (int mi = 0; mi < 4; ++mi) {
                const uint32_t r = ka + mi * 16 * PITCH;
                a[mi][0] = lds32(r);
                a[mi][1] = lds32(r + 8 * PITCH);
                a[mi][2] = lds32(r + 16);
                a[mi][3] = lds32(r + 8 * PITCH + 16);
            }
#pragma unroll
            for (int ni = 0; ni < 4; ++ni) {
                const uint32_t r = kb + ni * 8 * PITCH;
                bfr[ni][0] = lds32(r);
                bfr[ni][1] = lds32(r + 16);
            }
#pragma unroll
            for (int mi = 0; mi < 4; ++mi)
#pragma unroll
                for (int ni = 0; ni < 4; ++ni)
                    mma16816(acc[mi][ni], a[mi][0], a[mi][1], a[mi][2], a[mi][3],
                             bfr[ni][0], bfr[ni][1]);
        }
        __syncthreads();     // compute on buf done before it can be re-filled
    }

    // Epilogue: bias + store. c frag: rows g, g+8; cols tg*2, tg*2+1.
    const float* sbias = (const float*)(smem + OFF_BIAS);
#pragma unroll
    for (int mi = 0; mi < 4; ++mi) {
        const int r0 = m0 + wm * 64 + mi * 16 + g;
#pragma unroll
        for (int ni = 0; ni < 4; ++ni) {
            const int c = wn * 32 + ni * 8 + tg * 2;
            const float b0 = sbias[c], b1 = sbias[c + 1];
            float2 v0 = make_float2(acc[mi][ni][0] + b0, acc[mi][ni][1] + b1);
            float2 v1 = make_float2(acc[mi][ni][2] + b0, acc[mi][ni][3] + b1);
            *(float2*)(out + (size_t)r0 * COUT + c)       = v0;
            *(float2*)(out + (size_t)(r0 + 8) * COUT + c) = v1;
        }
    }
}

// ---------------------------------------------------------------------------
extern "C" void kernel_launch(void* const* d_in, const int* in_sizes, int n_in,
                              void* d_out, int out_size)
{
    const float* input_feat = (const float*)d_in[0];
    const int*   nbr_raw    = (const int*)d_in[1];
    const float* wnet       = (const float*)d_in[2];
    const float* addf       = (const float*)d_in[3];
    const float* W          = (const float*)d_in[4];
    const float* bias       = (const float*)d_in[5];
    float*       out        = (float*)d_out;

    static bool attr_set = false;
    if (!attr_set) {
        cudaFuncSetAttribute(gemm_mma_kernel,
                             cudaFuncAttributeMaxDynamicSharedMemorySize, SMEM_BYTES);
        attr_set = true;
    }

    detect_idx_kernel<<<1, 32>>>(nbr_raw);
    wconv_kernel<<<(COUT * KPAD + 255) / 256, 256>>>(W);
    pconv_kernel<<<NPTS / 4, 128>>>(input_feat, nbr_raw, wnet, addf);
    gemm_mma_kernel<<<NPTS / 128, 256, SMEM_BYTES>>>(bias, out);
}

// round 13
// speedup vs baseline: 1.6142x; 1.6142x over previous
#include <cuda_runtime.h>
#include <cuda_fp16.h>
#include <cstdint>

// Problem constants
#define BQ    2
#define NPT   65536
#define KN    16
#define CIN   64
#define CADD  3
#define CTOT  67
#define CPAD  68
#define CMID  16
#define INF   1072        // CTOT * CMID
#define KPAD  1088        // padded to 17*64
#define COUT  128
#define NPTS  (BQ * NPT)  // 131072

// fp16 scratch: pconv output [M][KPAD] (285 MB) + converted weights
__device__ __half g_a16[(size_t)NPTS * KPAD];
__device__ __half g_w16[(size_t)COUT * KPAD];
__device__ int g_idx_is64;

// ---------------------------------------------------------------------------
// Helpers
// ---------------------------------------------------------------------------
__device__ __forceinline__ uint32_t smem_u32(const void* p) {
    uint32_t a;
    asm("{ .reg .u64 t; cvta.to.shared.u64 t, %1; cvt.u32.u64 %0, t; }"
        : "=r"(a) : "l"(p));
    return a;
}
__device__ __forceinline__ void cp16(uint32_t sa, const void* g) {
    asm volatile("cp.async.cg.shared.global [%0], [%1], 16;" :: "r"(sa), "l"(g));
}
#define CP_COMMIT() asm volatile("cp.async.commit_group;" ::: "memory")
#define CP_WAIT0()  asm volatile("cp.async.wait_group 0;" ::: "memory")

__device__ __forceinline__ void ldsm_x4(uint32_t& r0, uint32_t& r1,
                                        uint32_t& r2, uint32_t& r3, uint32_t a) {
    asm volatile("ldmatrix.sync.aligned.m8n8.x4.shared.b16 {%0,%1,%2,%3}, [%4];"
                 : "=r"(r0), "=r"(r1), "=r"(r2), "=r"(r3) : "r"(a));
}
__device__ __forceinline__ void ldsm_x2(uint32_t& r0, uint32_t& r1, uint32_t a) {
    asm volatile("ldmatrix.sync.aligned.m8n8.x2.shared.b16 {%0,%1}, [%2];"
                 : "=r"(r0), "=r"(r1) : "r"(a));
}

__device__ __forceinline__ void mma16816(float* c, uint32_t a0, uint32_t a1,
                                         uint32_t a2, uint32_t a3,
                                         uint32_t b0, uint32_t b1) {
    asm volatile(
        "mma.sync.aligned.m16n8k16.row.col.f32.f16.f16.f32 "
        "{%0,%1,%2,%3}, {%4,%5,%6,%7}, {%8,%9}, {%0,%1,%2,%3};"
        : "+f"(c[0]), "+f"(c[1]), "+f"(c[2]), "+f"(c[3])
        : "r"(a0), "r"(a1), "r"(a2), "r"(a3), "r"(b0), "r"(b1));
}

// ---------------------------------------------------------------------------
// Kernel 0: detect index dtype (int64 vs int32 layout). Values < 65536, so an
// int64 buffer has all-zero odd 32-bit words. Reads 128B, in-bounds either way.
// ---------------------------------------------------------------------------
__global__ void detect_idx_kernel(const int* __restrict__ idx_raw)
{
    if (threadIdx.x == 0 && blockIdx.x == 0) {
        int nz = 0;
#pragma unroll
        for (int i = 1; i < 32; i += 2) nz |= idx_raw[i];
        g_idx_is64 = (nz == 0) ? 1 : 0;
    }
}

// ---------------------------------------------------------------------------
// Kernel W: convert linear_weight to fp16, zero-padded to KPAD
// ---------------------------------------------------------------------------
__global__ void wconv_kernel(const float* __restrict__ W)
{
    int idx = blockIdx.x * 256 + threadIdx.x;
    if (idx >= COUT * KPAD) return;
    int row = idx / KPAD, col = idx % KPAD;
    float x = (col < INF) ? W[row * INF + col] : 0.f;
    g_w16[idx] = __float2half_rn(x);
}

// ---------------------------------------------------------------------------
// fp16 store of a 16-float block (32 B = 2 uint4)
// ---------------------------------------------------------------------------
__device__ __forceinline__ void store_half16(__half* dst, const float* a)
{
    uint32_t h[8];
#pragma unroll
    for (int q = 0; q < 8; ++q) {
        __half2 v = __float22half2_rn(make_float2(a[2 * q], a[2 * q + 1]));
        h[q] = *(uint32_t*)&v;
    }
    ((uint4*)dst)[0] = make_uint4(h[0], h[1], h[2], h[3]);
    ((uint4*)dst)[1] = make_uint4(h[4], h[5], h[6], h[7]);
}

// ---------------------------------------------------------------------------
// Kernel 1: gather + weighted neighbor reduction -> fp16 rows [KPAD]
// One warp per point; 4 points per 128-thread block. (R10 version, measured.)
// ---------------------------------------------------------------------------
__global__ void __launch_bounds__(128, 8)
pconv_kernel(const float* __restrict__ input_feat,
             const int* __restrict__ nbr_raw,
             const float* __restrict__ wnet,
             const float* __restrict__ addf)
{
    const int warp = threadIdx.x >> 5;
    const int lane = threadIdx.x & 31;
    const int p = blockIdx.x * 4 + warp;
    const int b = p >> 16;

    __shared__ __align__(16) float fs[4][KN][CPAD];
    __shared__ __align__(16) float ws[4][KN][CMID];

    const float* featbase = input_feat + (size_t)b * NPT * CIN;
    const float* wp = wnet + (size_t)p * KN * CMID;
    const float* ap = addf + (size_t)p * KN * CADD;

    {
        const float4* w4 = (const float4*)wp;
        float4* s4 = (float4*)(&ws[warp][0][0]);
        s4[lane]      = w4[lane];
        s4[lane + 32] = w4[lane + 32];
    }

    const int stride = g_idx_is64 ? 2 : 1;
    const int* inds = nbr_raw + (size_t)p * KN * stride;
    int myidx = 0;
    if (lane < KN) {
        myidx = inds[lane * stride];
        myidx = min(max(myidx, 0), NPT - 1);
    }

#pragma unroll 4
    for (int k = 0; k < KN; ++k) {
        int r = __shfl_sync(0xffffffffu, myidx, k);
        const float* src = featbase + (size_t)r * CIN;
        fs[warp][k][lane]      = src[lane];
        fs[warp][k][lane + 32] = src[lane + 32];
    }
    if (lane < KN) {
        fs[warp][lane][64] = ap[lane * 3 + 0];
        fs[warp][lane][65] = ap[lane * 3 + 1];
        fs[warp][lane][66] = ap[lane * 3 + 2];
    }
    __syncwarp();

    float acc0[CMID], acc1[CMID], acc2[CMID];
#pragma unroll
    for (int j = 0; j < CMID; ++j) { acc0[j] = 0.f; acc1[j] = 0.f; acc2[j] = 0.f; }

    const bool has_c2 = (lane < 3);
#pragma unroll
    for (int k = 0; k < KN; ++k) {
        float wk[CMID];
#pragma unroll
        for (int j = 0; j < CMID; ++j) wk[j] = ws[warp][k][j];
        float f0 = fs[warp][k][lane];
        float f1 = fs[warp][k][lane + 32];
        float f2 = has_c2 ? fs[warp][k][lane + 64] : 0.f;
#pragma unroll
        for (int j = 0; j < CMID; ++j) {
            acc0[j] += f0 * wk[j];
            acc1[j] += f1 * wk[j];
            acc2[j] += f2 * wk[j];
        }
    }

    __half* orow = g_a16 + (size_t)p * KPAD;
    store_half16(orow + (size_t)lane * CMID,        acc0);
    store_half16(orow + (size_t)(lane + 32) * CMID, acc1);
    if (has_c2)
        store_half16(orow + (size_t)(lane + 64) * CMID, acc2);
    if (lane == 3) {   // zero pad cols 1072..1087
        uint4 z = make_uint4(0, 0, 0, 0);
        ((uint4*)(orow + INF))[0] = z;
        ((uint4*)(orow + INF))[1] = z;
    }
}

// ---------------------------------------------------------------------------
// Kernel 2: fp16 mma.sync GEMM   out[M,128] = A[M,KPAD] @ W[128,KPAD]^T + bias
// CTA 128x128, 8 warps (2x4), warp tile 64x32 = 4x4 m16n8k16 frags, fp32 acc.
// R10 2-stage cp.async structure (measured good); fragment loads via
// ldmatrix.x4/.x2 (8 instr per k16-step instead of 24 scalar LDS).
// PITCH=144: ldmatrix row addrs hit banks 4r..4r+3 -> all 32 banks once.
// ---------------------------------------------------------------------------
#define KSTG   64
#define PITCH  144                    // bytes per smem row (72 halves)
#define TILEB  (128 * PITCH)          // 18432 B per matrix per stage
#define OFF_A  0
#define OFF_W  (2 * TILEB)
#define OFF_BIAS (4 * TILEB)
#define SMEM_BYTES (4 * TILEB + 512)  // 74240
#define NSTG   (KPAD / KSTG)          // 17

__global__ void __launch_bounds__(256, 2)
gemm_mma_kernel(const float* __restrict__ bias, float* __restrict__ out)
{
    extern __shared__ char smem[];
    const uint32_t sb = smem_u32(smem);
    const int t = threadIdx.x;
    const int wid = t >> 5, lane = t & 31;
    const int wm = wid >> 2, wn = wid & 3;          // warp grid 2(M) x 4(N)
    const int g = lane >> 2, tg = lane & 3;         // mma lane decomposition
    const int m0 = blockIdx.x * 128;

    if (t < COUT) ((float*)(smem + OFF_BIAS))[t] = bias[t];

    // ldmatrix per-lane source rows:
    // x4 (A, 16x16): matrix m = lane/8, row r = lane%8;
    //   row offset = (m&1)*8 + r, col offset = (m>>1)*16 bytes
    // x2 (B, 8x16): lanes 0-15, matrix m2 = (lane>>3)&1 -> col offset m2*16
    const int lr8 = lane & 7;
    const int lm  = lane >> 3;                      // 0..3
    uint32_t aOff[4], bOff[4];
#pragma unroll
    for (int mi = 0; mi < 4; ++mi)
        aOff[mi] = (uint32_t)((wm * 64 + mi * 16 + (lm & 1) * 8 + lr8) * PITCH
                              + (lm >> 1) * 16);
#pragma unroll
    for (int ni = 0; ni < 4; ++ni)
        bOff[ni] = (uint32_t)((wn * 32 + ni * 8 + lr8) * PITCH + (lm & 1) * 16);

    const int lrow = t >> 1;                        // 0..127
    const int lc8a = (t & 1) * 4;                   // base c8 (0 or 4)

    auto issue_stage = [&](int s, int buf) {
        const int k0 = s * KSTG;
#pragma unroll
        for (int i = 0; i < 4; ++i) {
            const int c8 = lc8a + i;                // 8 halves each
            const uint32_t so = lrow * PITCH + c8 * 16;
            cp16(sb + OFF_A + buf * TILEB + so,
                 g_a16 + (size_t)(m0 + lrow) * KPAD + k0 + c8 * 8);
            cp16(sb + OFF_W + buf * TILEB + so,
                 g_w16 + (size_t)lrow * KPAD + k0 + c8 * 8);
        }
        CP_COMMIT();
    };

    float acc[4][4][4];
#pragma unroll
    for (int mi = 0; mi < 4; ++mi)
#pragma unroll
        for (int ni = 0; ni < 4; ++ni)
#pragma unroll
            for (int q = 0; q < 4; ++q) acc[mi][ni][q] = 0.f;

    issue_stage(0, 0);
    CP_WAIT0();
    __syncthreads();

    for (int s = 0; s < NSTG; ++s) {
        const int cur = s & 1, nxt = cur ^ 1;
        if (s + 1 < NSTG) issue_stage(s + 1, nxt);

        const uint32_t aT = sb + OFF_A + cur * TILEB;
        const uint32_t bT = sb + OFF_W + cur * TILEB;
#pragma unroll
        for (int kk = 0; kk < 4; ++kk) {            // 4 k16-steps per stage
            const uint32_t kcol = kk * 32;          // 16 halves = 32 B
            uint32_t a[4][4], bfr[4][2];
#pragma unroll
            for (int mi = 0; mi < 4; ++mi)
                ldsm_x4(a[mi][0], a[mi][1], a[mi][2], a[mi][3],
                        aT + aOff[mi] + kcol);
#pragma unroll
            for (int ni = 0; ni < 4; ++ni)
                ldsm_x2(bfr[ni][0], bfr[ni][1], bT + bOff[ni] + kcol);
#pragma unroll
            for (int mi = 0; mi < 4; ++mi)
#pragma unroll
                for (int ni = 0; ni < 4; ++ni)
                    mma16816(acc[mi][ni], a[mi][0], a[mi][1], a[mi][2], a[mi][3],
                             bfr[ni][0], bfr[ni][1]);
        }
        CP_WAIT0();
        __syncthreads();
    }

    // Epilogue: bias + store. c frag: rows g, g+8; cols tg*2, tg*2+1.
    const float* sbias = (const float*)(smem + OFF_BIAS);
#pragma unroll
    for (int mi = 0; mi < 4; ++mi) {
        const int r0 = m0 + wm * 64 + mi * 16 + g;
#pragma unroll
        for (int ni = 0; ni < 4; ++ni) {
            const int c = wn * 32 + ni * 8 + tg * 2;
            const float b0 = sbias[c], b1 = sbias[c + 1];
            float2 v0 = make_float2(acc[mi][ni][0] + b0, acc[mi][ni][1] + b1);
            float2 v1 = make_float2(acc[mi][ni][2] + b0, acc[mi][ni][3] + b1);
            *(float2*)(out + (size_t)r0 * COUT + c)       = v0;
            *(float2*)(out + (size_t)(r0 + 8) * COUT + c) = v1;
        }
    }
}

// ---------------------------------------------------------------------------
extern "C" void kernel_launch(void* const* d_in, const int* in_sizes, int n_in,
                              void* d_out, int out_size)
{
    const float* input_feat = (const float*)d_in[0];
    const int*   nbr_raw    = (const int*)d_in[1];
    const float* wnet       = (const float*)d_in[2];
    const float* addf       = (const float*)d_in[3];
    const float* W          = (const float*)d_in[4];
    const float* bias       = (const float*)d_in[5];
    float*       out        = (float*)d_out;

    static bool attr_set = false;
    if (!attr_set) {
        cudaFuncSetAttribute(gemm_mma_kernel,
                             cudaFuncAttributeMaxDynamicSharedMemorySize, SMEM_BYTES);
        attr_set = true;
    }

    detect_idx_kernel<<<1, 32>>>(nbr_raw);
    wconv_kernel<<<(COUT * KPAD + 255) / 256, 256>>>(W);
    pconv_kernel<<<NPTS / 4, 128>>>(input_feat, nbr_raw, wnet, addf);
    gemm_mma_kernel<<<NPTS / 128, 256, SMEM_BYTES>>>(bias, out);
}

// round 15
// speedup vs baseline: 1.6689x; 1.0339x over previous
#include <cuda_runtime.h>
#include <cuda_fp16.h>
#include <cstdint>

// Problem constants
#define BQ    2
#define NPT   65536
#define KN    16
#define CIN   64
#define CADD  3
#define CTOT  67
#define CPAD  68
#define CMID  16
#define INF   1072        // CTOT * CMID
#define KPAD  1088        // padded to 17*64
#define COUT  128
#define NPTS  (BQ * NPT)  // 131072

// fp16 scratch: pconv output [M][KPAD] (285 MB) + converted weights
__device__ __half g_a16[(size_t)NPTS * KPAD];
__device__ __half g_w16[(size_t)COUT * KPAD];
__device__ int g_idx_is64;

// ---------------------------------------------------------------------------
// Helpers
// ---------------------------------------------------------------------------
__device__ __forceinline__ uint32_t smem_u32(const void* p) {
    uint32_t a;
    asm("{ .reg .u64 t; cvta.to.shared.u64 t, %1; cvt.u32.u64 %0, t; }"
        : "=r"(a) : "l"(p));
    return a;
}
__device__ __forceinline__ void cp16(uint32_t sa, const void* g) {
    asm volatile("cp.async.cg.shared.global [%0], [%1], 16;" :: "r"(sa), "l"(g));
}
#define CP_COMMIT() asm volatile("cp.async.commit_group;" ::: "memory")
#define CP_WAIT0()  asm volatile("cp.async.wait_group 0;" ::: "memory")

__device__ __forceinline__ void ldsm_x4(uint32_t& r0, uint32_t& r1,
                                        uint32_t& r2, uint32_t& r3, uint32_t a) {
    asm volatile("ldmatrix.sync.aligned.m8n8.x4.shared.b16 {%0,%1,%2,%3}, [%4];"
                 : "=r"(r0), "=r"(r1), "=r"(r2), "=r"(r3) : "r"(a));
}
__device__ __forceinline__ void ldsm_x2(uint32_t& r0, uint32_t& r1, uint32_t a) {
    asm volatile("ldmatrix.sync.aligned.m8n8.x2.shared.b16 {%0,%1}, [%2];"
                 : "=r"(r0), "=r"(r1) : "r"(a));
}

__device__ __forceinline__ void mma16816(float* c, uint32_t a0, uint32_t a1,
                                         uint32_t a2, uint32_t a3,
                                         uint32_t b0, uint32_t b1) {
    asm volatile(
        "mma.sync.aligned.m16n8k16.row.col.f32.f16.f16.f32 "
        "{%0,%1,%2,%3}, {%4,%5,%6,%7}, {%8,%9}, {%0,%1,%2,%3};"
        : "+f"(c[0]), "+f"(c[1]), "+f"(c[2]), "+f"(c[3])
        : "r"(a0), "r"(a1), "r"(a2), "r"(a3), "r"(b0), "r"(b1));
}

// ---------------------------------------------------------------------------
// Kernel 0: detect index dtype (int64 vs int32 layout). Values < 65536, so an
// int64 buffer has all-zero odd 32-bit words. Reads 128B, in-bounds either way.
// ---------------------------------------------------------------------------
__global__ void detect_idx_kernel(const int* __restrict__ idx_raw)
{
    if (threadIdx.x == 0 && blockIdx.x == 0) {
        int nz = 0;
#pragma unroll
        for (int i = 1; i < 32; i += 2) nz |= idx_raw[i];
        g_idx_is64 = (nz == 0) ? 1 : 0;
    }
}

// ---------------------------------------------------------------------------
// Kernel W: convert linear_weight to fp16, zero-padded to KPAD
// ---------------------------------------------------------------------------
__global__ void wconv_kernel(const float* __restrict__ W)
{
    int idx = blockIdx.x * 256 + threadIdx.x;
    if (idx >= COUT * KPAD) return;
    int row = idx / KPAD, col = idx % KPAD;
    float x = (col < INF) ? W[row * INF + col] : 0.f;
    g_w16[idx] = __float2half_rn(x);
}

// ---------------------------------------------------------------------------
// fp16 store of a 16-float block (32 B = 2 uint4)
// ---------------------------------------------------------------------------
__device__ __forceinline__ void store_half16(__half* dst, const float* a)
{
    uint32_t h[8];
#pragma unroll
    for (int q = 0; q < 8; ++q) {
        __half2 v = __float22half2_rn(make_float2(a[2 * q], a[2 * q + 1]));
        h[q] = *(uint32_t*)&v;
    }
    ((uint4*)dst)[0] = make_uint4(h[0], h[1], h[2], h[3]);
    ((uint4*)dst)[1] = make_uint4(h[4], h[5], h[6], h[7]);
}

// ---------------------------------------------------------------------------
// Kernel 1: gather + weighted neighbor reduction -> fp16 rows [KPAD]
// One warp per point; 4 points per 128-thread block.
// Main loop: each lane owns c = lane and lane+32 (64 channels, no wasted
// issue). The 3 additional-feature channels (48 outputs, contiguous at
// orow[1024..1071]) are handled in a short epilogue: lane l computes output
// 1024+l, lanes 0-15 also 1056+l. Same per-output accumulation order as
// before -> bit-identical results.
// ---------------------------------------------------------------------------
__global__ void __launch_bounds__(128, 6)
pconv_kernel(const float* __restrict__ input_feat,
             const int* __restrict__ nbr_raw,
             const float* __restrict__ wnet,
             const float* __restrict__ addf)
{
    const int warp = threadIdx.x >> 5;
    const int lane = threadIdx.x & 31;
    const int p = blockIdx.x * 4 + warp;
    const int b = p >> 16;

    __shared__ __align__(16) float fs[4][KN][CPAD];
    __shared__ __align__(16) float ws[4][KN][CMID];

    const float* featbase = input_feat + (size_t)b * NPT * CIN;
    const float* wp = wnet + (size_t)p * KN * CMID;
    const float* ap = addf + (size_t)p * KN * CADD;

    {
        const float4* w4 = (const float4*)wp;
        float4* s4 = (float4*)(&ws[warp][0][0]);
        s4[lane]      = w4[lane];
        s4[lane + 32] = w4[lane + 32];
    }

    const int stride = g_idx_is64 ? 2 : 1;
    const int* inds = nbr_raw + (size_t)p * KN * stride;
    int myidx = 0;
    if (lane < KN) {
        myidx = inds[lane * stride];
        myidx = min(max(myidx, 0), NPT - 1);
    }

#pragma unroll 4
    for (int k = 0; k < KN; ++k) {
        int r = __shfl_sync(0xffffffffu, myidx, k);
        const float* src = featbase + (size_t)r * CIN;
        fs[warp][k][lane]      = src[lane];
        fs[warp][k][lane + 32] = src[lane + 32];
    }
    if (lane < KN) {
        fs[warp][lane][64] = ap[lane * 3 + 0];
        fs[warp][lane][65] = ap[lane * 3 + 1];
        fs[warp][lane][66] = ap[lane * 3 + 2];
    }
    __syncwarp();

    // Main: c = lane (acc0) and c = lane+32 (acc1); all lanes useful.
    float acc0[CMID], acc1[CMID];
#pragma unroll
    for (int j = 0; j < CMID; ++j) { acc0[j] = 0.f; acc1[j] = 0.f; }

#pragma unroll
    for (int k = 0; k < KN; ++k) {
        float wk[CMID];
#pragma unroll
        for (int j = 0; j < CMID; ++j) wk[j] = ws[warp][k][j];
        float f0 = fs[warp][k][lane];
        float f1 = fs[warp][k][lane + 32];
#pragma unroll
        for (int j = 0; j < CMID; ++j) {
            acc0[j] += f0 * wk[j];
            acc1[j] += f1 * wk[j];
        }
    }

    __half* orow = g_a16 + (size_t)p * KPAD;
    store_half16(orow + (size_t)lane * CMID,        acc0);
    store_half16(orow + (size_t)(lane + 32) * CMID, acc1);

    // Epilogue: additional-feature channels (c = 64..66). 48 outputs land
    // contiguously at orow[1024 + o], o = (c-64)*16 + j.
    {
        const int o0 = lane;              // 0..31
        const int c0x = 64 + (o0 >> 4), j0 = o0 & 15;
        const int o1 = lane + 32;         // 32..47 (lanes 0..15)
        const int c1x = 64 + (o1 >> 4), j1 = o1 & 15;
        float e0 = 0.f, e1 = 0.f;
#pragma unroll
        for (int k = 0; k < KN; ++k) {
            e0 += fs[warp][k][c0x] * ws[warp][k][j0];
            e1 += fs[warp][k][c1x] * ws[warp][k][j1];
        }
        orow[1024 + o0] = __float2half_rn(e0);
        if (lane < 16) orow[1024 + o1] = __float2half_rn(e1);
    }

    if (lane == 3) {   // zero pad cols 1072..1087
        uint4 z = make_uint4(0, 0, 0, 0);
        ((uint4*)(orow + INF))[0] = z;
        ((uint4*)(orow + INF))[1] = z;
    }
}

// ---------------------------------------------------------------------------
// Kernel 2: fp16 mma.sync GEMM   out[M,128] = A[M,KPAD] @ W[128,KPAD]^T + bias
// (R13 version, measured 154 us — unchanged.)
// ---------------------------------------------------------------------------
#define KSTG   64
#define PITCH  144                    // bytes per smem row (72 halves)
#define TILEB  (128 * PITCH)          // 18432 B per matrix per stage
#define OFF_A  0
#define OFF_W  (2 * TILEB)
#define OFF_BIAS (4 * TILEB)
#define SMEM_BYTES (4 * TILEB + 512)  // 74240
#define NSTG   (KPAD / KSTG)          // 17

__global__ void __launch_bounds__(256, 2)
gemm_mma_kernel(const float* __restrict__ bias, float* __restrict__ out)
{
    extern __shared__ char smem[];
    const uint32_t sb = smem_u32(smem);
    const int t = threadIdx.x;
    const int wid = t >> 5, lane = t & 31;
    const int wm = wid >> 2, wn = wid & 3;          // warp grid 2(M) x 4(N)
    const int g = lane >> 2, tg = lane & 3;         // mma lane decomposition
    const int m0 = blockIdx.x * 128;

    if (t < COUT) ((float*)(smem + OFF_BIAS))[t] = bias[t];

    const int lr8 = lane & 7;
    const int lm  = lane >> 3;                      // 0..3
    uint32_t aOff[4], bOff[4];
#pragma unroll
    for (int mi = 0; mi < 4; ++mi)
        aOff[mi] = (uint32_t)((wm * 64 + mi * 16 + (lm & 1) * 8 + lr8) * PITCH
                              + (lm >> 1) * 16);
#pragma unroll
    for (int ni = 0; ni < 4; ++ni)
        bOff[ni] = (uint32_t)((wn * 32 + ni * 8 + lr8) * PITCH + (lm & 1) * 16);

    const int lrow = t >> 1;                        // 0..127
    const int lc8a = (t & 1) * 4;                   // base c8 (0 or 4)

    auto issue_stage = [&](int s, int buf) {
        const int k0 = s * KSTG;
#pragma unroll
        for (int i = 0; i < 4; ++i) {
            const int c8 = lc8a + i;                // 8 halves each
            const uint32_t so = lrow * PITCH + c8 * 16;
            cp16(sb + OFF_A + buf * TILEB + so,
                 g_a16 + (size_t)(m0 + lrow) * KPAD + k0 + c8 * 8);
            cp16(sb + OFF_W + buf * TILEB + so,
                 g_w16 + (size_t)lrow * KPAD + k0 + c8 * 8);
        }
        CP_COMMIT();
    };

    float acc[4][4][4];
#pragma unroll
    for (int mi = 0; mi < 4; ++mi)
#pragma unroll
        for (int ni = 0; ni < 4; ++ni)
#pragma unroll
            for (int q = 0; q < 4; ++q) acc[mi][ni][q] = 0.f;

    issue_stage(0, 0);
    CP_WAIT0();
    __syncthreads();

    for (int s = 0; s < NSTG; ++s) {
        const int cur = s & 1, nxt = cur ^ 1;
        if (s + 1 < NSTG) issue_stage(s + 1, nxt);

        const uint32_t aT = sb + OFF_A + cur * TILEB;
        const uint32_t bT = sb + OFF_W + cur * TILEB;
#pragma unroll
        for (int kk = 0; kk < 4; ++kk) {            // 4 k16-steps per stage
            const uint32_t kcol = kk * 32;          // 16 halves = 32 B
            uint32_t a[4][4], bfr[4][2];
#pragma unroll
            for (int mi = 0; mi < 4; ++mi)
                ldsm_x4(a[mi][0], a[mi][1], a[mi][2], a[mi][3],
                        aT + aOff[mi] + kcol);
#pragma unroll
            for (int ni = 0; ni < 4; ++ni)
                ldsm_x2(bfr[ni][0], bfr[ni][1], bT + bOff[ni] + kcol);
#pragma unroll
            for (int mi = 0; mi < 4; ++mi)
#pragma unroll
                for (int ni = 0; ni < 4; ++ni)
                    mma16816(acc[mi][ni], a[mi][0], a[mi][1], a[mi][2], a[mi][3],
                             bfr[ni][0], bfr[ni][1]);
        }
        CP_WAIT0();
        __syncthreads();
    }

    // Epilogue: bias + store. c frag: rows g, g+8; cols tg*2, tg*2+1.
    const float* sbias = (const float*)(smem + OFF_BIAS);
#pragma unroll
    for (int mi = 0; mi < 4; ++mi) {
        const int r0 = m0 + wm * 64 + mi * 16 + g;
#pragma unroll
        for (int ni = 0; ni < 4; ++ni) {
            const int c = wn * 32 + ni * 8 + tg * 2;
            const float b0 = sbias[c], b1 = sbias[c + 1];
            float2 v0 = make_float2(acc[mi][ni][0] + b0, acc[mi][ni][1] + b1);
            float2 v1 = make_float2(acc[mi][ni][2] + b0, acc[mi][ni][3] + b1);
            *(float2*)(out + (size_t)r0 * COUT + c)       = v0;
            *(float2*)(out + (size_t)(r0 + 8) * COUT + c) = v1;
        }
    }
}

// ---------------------------------------------------------------------------
extern "C" void kernel_launch(void* const* d_in, const int* in_sizes, int n_in,
                              void* d_out, int out_size)
{
    const float* input_feat = (const float*)d_in[0];
    const int*   nbr_raw    = (const int*)d_in[1];
    const float* wnet       = (const float*)d_in[2];
    const float* addf       = (const float*)d_in[3];
    const float* W          = (const float*)d_in[4];
    const float* bias       = (const float*)d_in[5];
    float*       out        = (float*)d_out;

    static bool attr_set = false;
    if (!attr_set) {
        cudaFuncSetAttribute(gemm_mma_kernel,
                             cudaFuncAttributeMaxDynamicSharedMemorySize, SMEM_BYTES);
        attr_set = true;
    }

    detect_idx_kernel<<<1, 32>>>(nbr_raw);
    wconv_kernel<<<(COUT * KPAD + 255) / 256, 256>>>(W);
    pconv_kernel<<<NPTS / 4, 128>>>(input_feat, nbr_raw, wnet, addf);
    gemm_mma_kernel<<<NPTS / 128, 256, SMEM_BYTES>>>(bias, out);
}